// round 6
// baseline (speedup 1.0000x reference)
#include <cuda_runtime.h>
#include <cuda_bf16.h>
#include <math.h>
#include <stdint.h>

#define BB 2
#define TT 2048
#define DD 1024
#define NH 16
#define NKV 4
#define HD 64
#define NREP 4           // NH / NKV
#define MM (BB*TT)       // 4096
#define NQKV (NH*HD + 2*NKV*HD)   // 1536 fused QKV output width

// ---------------- scratch (device globals; no runtime allocation) -----------
__device__ float g_qkv[MM*NQKV];            // fused QKV proj out (fp32)
__device__ __align__(16) float g_cos[TT*32];
__device__ __align__(16) float g_sin[TT*32];
__device__ __nv_bfloat16 g_xhi[MM*DD],  g_xlo[MM*DD];
__device__ __nv_bfloat16 g_ahi[MM*DD],  g_alo[MM*DD];          // attention out (bf16 split)
__device__ __nv_bfloat16 g_wt_hi[NQKV*DD], g_wt_lo[NQKV*DD];   // fused QKV weights^T [N][K]
__device__ __nv_bfloat16 g_wot_hi[DD*DD],  g_wot_lo[DD*DD];    // Wo^T [N][K]
__device__ __nv_bfloat16 g_qhi[BB*NH*TT*HD],  g_qlo[BB*NH*TT*HD];
__device__ __nv_bfloat16 g_khi[BB*NKV*TT*HD], g_klo[BB*NKV*TT*HD];
__device__ __nv_bfloat16 g_vthi[BB*NKV*HD*TT], g_vtlo[BB*NKV*HD*TT];

// ---------------- helpers ----------------------------------------------------
__device__ __forceinline__ uint32_t smem_u32(const void* p) {
    uint32_t a;
    asm("{ .reg .u64 t; cvta.to.shared.u64 t, %1; cvt.u32.u64 %0, t; }"
        : "=r"(a) : "l"(p));
    return a;
}
#define SWZ(off) ((off) ^ (((off) >> 3) & 0x70))

#define CP_ASYNC16(dst, src) \
    asm volatile("cp.async.cg.shared.global [%0], [%1], 16;" \
                 :: "r"(dst), "l"(src) : "memory")
#define CP_COMMIT() asm volatile("cp.async.commit_group;" ::: "memory")
#define CP_WAIT(n)  asm volatile("cp.async.wait_group %0;" :: "n"(n) : "memory")

#define LDSM4(r0, r1, r2, r3, addr) \
    asm volatile("ldmatrix.sync.aligned.m8n8.x4.shared.b16 {%0,%1,%2,%3}, [%4];" \
                 : "=r"(r0), "=r"(r1), "=r"(r2), "=r"(r3) : "r"(addr))

#define MMAS(c, a, b0, b1) \
    asm volatile("mma.sync.aligned.m16n8k16.row.col.f32.bf16.bf16.f32 " \
                 "{%0,%1,%2,%3}, {%4,%5,%6,%7}, {%8,%9}, {%0,%1,%2,%3};" \
                 : "+f"((c)[0]), "+f"((c)[1]), "+f"((c)[2]), "+f"((c)[3]) \
                 : "r"((a)[0]), "r"((a)[1]), "r"((a)[2]), "r"((a)[3]), \
                   "r"(b0), "r"(b1))

__device__ __forceinline__ void split2(float x0, float x1, uint32_t& hi, uint32_t& lo) {
    __nv_bfloat16 h0 = __float2bfloat16(x0), h1 = __float2bfloat16(x1);
    float r0 = x0 - __bfloat162float(h0), r1 = x1 - __bfloat162float(h1);
    __nv_bfloat162 H; H.x = h0; H.y = h1;
    __nv_bfloat162 L = __floats2bfloat162_rn(r0, r1);
    hi = *(uint32_t*)&H; lo = *(uint32_t*)&L;
}

// ---------------------------------------------------------------------------
// Split-bf16 HMMA GEMM: C[M,N] = (Ahi+Alo)[M,K] @ (Bhi+Blo)[N,K]^T (fp32 acc)
// 128x256 CTA tile, 8 warps (2m x 4n, warp tile 64x64), BK=64,
// cp.async 2-stage (2 x 96KB smem).
// ---------------------------------------------------------------------------
__global__ __launch_bounds__(256, 1) void gemm_mma(
        const __nv_bfloat16* __restrict__ Ahi, const __nv_bfloat16* __restrict__ Alo,
        const __nv_bfloat16* __restrict__ Bhi, const __nv_bfloat16* __restrict__ Blo,
        float* __restrict__ C, int M, int N, int K) {
    extern __shared__ char smem[];
    uint32_t sbase = smem_u32(smem);
    int tid = threadIdx.x, wid = tid >> 5, lid = tid & 31;
    int m0 = blockIdx.y * 128, n0 = blockIdx.x * 256;
    int wm = wid & 1, wn = wid >> 1;          // warp tile: m 64, n 64
    const int nch = K / 64;
    const int rr = tid >> 3;
    const int uu = tid & 7;

    float acc[4][8][4] = {};

    auto load_chunk = [&](int buf, int ch) {
        int k0 = ch * 64;
        uint32_t dbase = sbase + (uint32_t)buf * 98304u;
        #pragma unroll
        for (int arr = 0; arr < 2; arr++) {             // A hi/lo: 128 rows
            const __nv_bfloat16* s = arr ? Alo : Ahi;
            uint32_t ab = dbase + (uint32_t)arr * 16384u;
            #pragma unroll
            for (int it = 0; it < 4; it++) {
                int r = it * 32 + rr;
                CP_ASYNC16(ab + SWZ(r * 128 + uu * 16),
                           s + (size_t)(m0 + r) * K + k0 + uu * 8);
            }
        }
        #pragma unroll
        for (int arr = 0; arr < 2; arr++) {             // B hi/lo: 256 rows
            const __nv_bfloat16* s = arr ? Blo : Bhi;
            uint32_t ab = dbase + 32768u + (uint32_t)arr * 32768u;
            #pragma unroll
            for (int it = 0; it < 8; it++) {
                int r = it * 32 + rr;
                CP_ASYNC16(ab + SWZ(r * 128 + uu * 16),
                           s + (size_t)(n0 + r) * K + k0 + uu * 8);
            }
        }
        CP_COMMIT();
    };

    load_chunk(0, 0);
    if (nch > 1) load_chunk(1, 1);

    for (int ch = 0; ch < nch; ch++) {
        if (ch < nch - 1) { CP_WAIT(1); } else { CP_WAIT(0); }
        __syncthreads();

        uint32_t db = sbase + (uint32_t)(ch & 1) * 98304u;
        uint32_t abh = db, abl = db + 16384u;
        uint32_t bbh = db + 32768u, bbl = db + 65536u;
        int g = lid >> 3, w8 = lid & 7;

        #pragma unroll
        for (int ks = 0; ks < 4; ks++) {
            uint32_t ah[4][4], al[4][4];
            int arow = wm * 64 + (lid & 15);
            int acol = ks * 32 + (lid >> 4) * 16;
            #pragma unroll
            for (int mi = 0; mi < 4; mi++) {
                uint32_t off = SWZ((arow + mi * 16) * 128 + acol);
                LDSM4(ah[mi][0], ah[mi][1], ah[mi][2], ah[mi][3], abh + off);
                LDSM4(al[mi][0], al[mi][1], al[mi][2], al[mi][3], abl + off);
            }
            #pragma unroll
            for (int p = 0; p < 4; p++) {
                int nrow = wn * 64 + p * 16 + (g >> 1) * 8 + w8;
                uint32_t off = SWZ(nrow * 128 + ks * 32 + (g & 1) * 16);
                uint32_t b0, b1, b2, b3, c0, c1, c2, c3;
                LDSM4(b0, b1, b2, b3, bbh + off);
                LDSM4(c0, c1, c2, c3, bbl + off);
                #pragma unroll
                for (int mi = 0; mi < 4; mi++) {
                    MMAS(acc[mi][2*p],   ah[mi], b0, b1);
                    MMAS(acc[mi][2*p+1], ah[mi], b2, b3);
                    MMAS(acc[mi][2*p],   ah[mi], c0, c1);
                    MMAS(acc[mi][2*p+1], ah[mi], c2, c3);
                    MMAS(acc[mi][2*p],   al[mi], b0, b1);
                    MMAS(acc[mi][2*p+1], al[mi], b2, b3);
                }
            }
        }
        __syncthreads();
        if (ch + 2 < nch) load_chunk(ch & 1, ch + 2);
    }

    #pragma unroll
    for (int mi = 0; mi < 4; mi++) {
        int row = m0 + wm * 64 + mi * 16 + (lid >> 2);
        #pragma unroll
        for (int ni = 0; ni < 8; ni++) {
            int col = n0 + wn * 64 + ni * 8 + (lid & 3) * 2;
            *(float2*)&C[(size_t)row * N + col] =
                make_float2(acc[mi][ni][0], acc[mi][ni][1]);
            *(float2*)&C[(size_t)(row + 8) * N + col] =
                make_float2(acc[mi][ni][2], acc[mi][ni][3]);
        }
    }
}

// ---------------------------------------------------------------------------
// HMMA flash attention, causal. Grid (T/128 reversed, B*NH), 256 threads.
// 3-stage cp.async pipeline; softmax in exp2 domain; fp32 accum.
// ---------------------------------------------------------------------------
__global__ __launch_bounds__(256, 1) void attn_mma(
        const __nv_bfloat16* __restrict__ Qhi, const __nv_bfloat16* __restrict__ Qlo,
        const __nv_bfloat16* __restrict__ Khi, const __nv_bfloat16* __restrict__ Klo,
        const __nv_bfloat16* __restrict__ Vthi, const __nv_bfloat16* __restrict__ Vtlo,
        __nv_bfloat16* __restrict__ Ohi, __nv_bfloat16* __restrict__ Olo) {
    extern __shared__ char smem[];
    uint32_t sbase = smem_u32(smem);
    const uint32_t QHI = 0, QLO = 16384, BUF = 32768;   // 3 chunk buffers of 32KB

    int tid = threadIdx.x, wid = tid >> 5, lid = tid & 31;
    int qt = gridDim.x - 1 - blockIdx.x;
    int bh = blockIdx.y;
    int b = bh / NH, h = bh % NH, kvh = h / NREP;
    int q0 = qt * 128;

    const __nv_bfloat16* qbh = Qhi + (size_t)(b * NH + h) * TT * HD;
    const __nv_bfloat16* qbl = Qlo + (size_t)(b * NH + h) * TT * HD;
    const __nv_bfloat16* kbh = Khi + (size_t)(b * NKV + kvh) * TT * HD;
    const __nv_bfloat16* kbl = Klo + (size_t)(b * NKV + kvh) * TT * HD;
    const __nv_bfloat16* vbh = Vthi + (size_t)(b * NKV + kvh) * HD * TT;
    const __nv_bfloat16* vbl = Vtlo + (size_t)(b * NKV + kvh) * HD * TT;

    // stage Q (own commit group)
    {
        #pragma unroll
        for (int arr = 0; arr < 2; arr++) {
            const __nv_bfloat16* s = arr ? qbl : qbh;
            uint32_t ab = sbase + (arr ? QLO : QHI);
            #pragma unroll
            for (int it = 0; it < 4; it++) {
                int idx = it * 256 + tid;
                int r = idx >> 3, u = idx & 7;
                CP_ASYNC16(ab + SWZ(r * 128 + u * 16),
                           s + (size_t)(q0 + r) * HD + u * 8);
            }
        }
        CP_COMMIT();
    }

    auto load_chunk = [&](int buf, int kt) {
        uint32_t db = sbase + BUF + (uint32_t)buf * 32768u;
        #pragma unroll
        for (int arr = 0; arr < 4; arr++) {
            uint32_t ab = db + (uint32_t)arr * 8192u;
            #pragma unroll
            for (int it = 0; it < 2; it++) {
                int idx = it * 256 + tid;
                int r = idx >> 3, u = idx & 7;
                const __nv_bfloat16* src;
                if (arr == 0)      src = kbh + (size_t)(kt * 64 + r) * HD + u * 8;
                else if (arr == 1) src = kbl + (size_t)(kt * 64 + r) * HD + u * 8;
                else if (arr == 2) src = vbh + (size_t)r * TT + kt * 64 + u * 8;
                else               src = vbl + (size_t)r * TT + kt * 64 + u * 8;
                CP_ASYNC16(ab + SWZ(r * 128 + u * 16), src);
            }
        }
        CP_COMMIT();
    };

    int nch = 2 * qt + 2;
    int issued = (nch > 1) ? 2 : 1;
    load_chunk(0, 0);
    if (nch > 1) load_chunk(1, 1);

    // Q fragments (wait leaves the chunk groups pending)
    if (issued == 2) { CP_WAIT(2); } else { CP_WAIT(1); }
    __syncthreads();
    uint32_t qfh[4][4], qfl[4][4];
    {
        int arow = wid * 16 + (lid & 15);
        #pragma unroll
        for (int ks = 0; ks < 4; ks++) {
            uint32_t off = SWZ(arow * 128 + ks * 32 + (lid >> 4) * 16);
            LDSM4(qfh[ks][0], qfh[ks][1], qfh[ks][2], qfh[ks][3], sbase + QHI + off);
            LDSM4(qfl[ks][0], qfl[ks][1], qfl[ks][2], qfl[ks][3], sbase + QLO + off);
        }
    }

    float oacc[8][4] = {};
    float mA = -1e30f, mB = -1e30f, lA = 0.f, lB = 0.f;
    const int g = lid >> 3, w8 = lid & 7;
    const int qrA = q0 + wid * 16 + (lid >> 2);
    const float SC = 0.125f * 1.4426950408889634f;   // scale * log2(e)

    for (int ch = 0; ch < nch; ch++) {
        if (issued - ch - 1 >= 1) { CP_WAIT(1); } else { CP_WAIT(0); }
        __syncthreads();
        // prefetch next (buffer (ch+2)%3 == (ch-1)%3 is free after the sync)
        if (issued < nch) { load_chunk(issued % 3, issued); issued++; }

        int kt = ch;
        bool active = (kt * 64 <= q0 + wid * 16 + 15);
        if (active) {
            uint32_t kb = sbase + BUF + (uint32_t)(ch % 3) * 32768u;
            uint32_t vb = kb + 16384u;

            // ---- S = Q K^T (3-term split) ----
            float sacc[8][4] = {};
            #pragma unroll
            for (int ks = 0; ks < 4; ks++) {
                #pragma unroll
                for (int p = 0; p < 4; p++) {
                    int nrow = p * 16 + (g >> 1) * 8 + w8;
                    uint32_t off = SWZ(nrow * 128 + ks * 32 + (g & 1) * 16);
                    uint32_t b0, b1, b2, b3, c0, c1, c2, c3;
                    LDSM4(b0, b1, b2, b3, kb + off);
                    LDSM4(c0, c1, c2, c3, kb + 8192u + off);
                    MMAS(sacc[2*p],   qfh[ks], b0, b1);
                    MMAS(sacc[2*p+1], qfh[ks], b2, b3);
                    MMAS(sacc[2*p],   qfh[ks], c0, c1);
                    MMAS(sacc[2*p+1], qfh[ks], c2, c3);
                    MMAS(sacc[2*p],   qfl[ks], b0, b1);
                    MMAS(sacc[2*p+1], qfl[ks], b2, b3);
                }
            }

            // ---- scale (log2 domain) + causal mask ----
            #pragma unroll
            for (int nt = 0; nt < 8; nt++) {
                int kc = kt * 64 + nt * 8 + (lid & 3) * 2;
                #pragma unroll
                for (int j = 0; j < 4; j++) sacc[nt][j] *= SC;
                if (kc > qrA)         sacc[nt][0] = -1e9f;
                if (kc + 1 > qrA)     sacc[nt][1] = -1e9f;
                if (kc > qrA + 8)     sacc[nt][2] = -1e9f;
                if (kc + 1 > qrA + 8) sacc[nt][3] = -1e9f;
            }

            // ---- online softmax (base-2) ----
            float rmA = -1e30f, rmB = -1e30f;
            #pragma unroll
            for (int nt = 0; nt < 8; nt++) {
                rmA = fmaxf(rmA, fmaxf(sacc[nt][0], sacc[nt][1]));
                rmB = fmaxf(rmB, fmaxf(sacc[nt][2], sacc[nt][3]));
            }
            rmA = fmaxf(rmA, __shfl_xor_sync(0xffffffffu, rmA, 1));
            rmA = fmaxf(rmA, __shfl_xor_sync(0xffffffffu, rmA, 2));
            rmB = fmaxf(rmB, __shfl_xor_sync(0xffffffffu, rmB, 1));
            rmB = fmaxf(rmB, __shfl_xor_sync(0xffffffffu, rmB, 2));
            float mnA = fmaxf(mA, rmA), mnB = fmaxf(mB, rmB);
            float corrA = exp2f(mA - mnA), corrB = exp2f(mB - mnB);
            mA = mnA; mB = mnB;
            float rsA = 0.f, rsB = 0.f;
            #pragma unroll
            for (int nt = 0; nt < 8; nt++) {
                sacc[nt][0] = exp2f(sacc[nt][0] - mA);
                sacc[nt][1] = exp2f(sacc[nt][1] - mA);
                sacc[nt][2] = exp2f(sacc[nt][2] - mB);
                sacc[nt][3] = exp2f(sacc[nt][3] - mB);
                rsA += sacc[nt][0] + sacc[nt][1];
                rsB += sacc[nt][2] + sacc[nt][3];
            }
            rsA += __shfl_xor_sync(0xffffffffu, rsA, 1);
            rsA += __shfl_xor_sync(0xffffffffu, rsA, 2);
            rsB += __shfl_xor_sync(0xffffffffu, rsB, 1);
            rsB += __shfl_xor_sync(0xffffffffu, rsB, 2);
            lA = lA * corrA + rsA;
            lB = lB * corrB + rsB;
            #pragma unroll
            for (int nt = 0; nt < 8; nt++) {
                oacc[nt][0] *= corrA; oacc[nt][1] *= corrA;
                oacc[nt][2] *= corrB; oacc[nt][3] *= corrB;
            }

            // ---- O += P V (P frags from S accs, 3-term split) ----
            #pragma unroll
            for (int k2 = 0; k2 < 4; k2++) {
                uint32_t pah[4], pal[4];
                split2(sacc[2*k2][0],   sacc[2*k2][1],   pah[0], pal[0]);
                split2(sacc[2*k2][2],   sacc[2*k2][3],   pah[1], pal[1]);
                split2(sacc[2*k2+1][0], sacc[2*k2+1][1], pah[2], pal[2]);
                split2(sacc[2*k2+1][2], sacc[2*k2+1][3], pah[3], pal[3]);
                #pragma unroll
                for (int p = 0; p < 4; p++) {
                    int nrow = p * 16 + (g >> 1) * 8 + w8;
                    uint32_t off = SWZ(nrow * 128 + k2 * 32 + (g & 1) * 16);
                    uint32_t b0, b1, b2, b3, c0, c1, c2, c3;
                    LDSM4(b0, b1, b2, b3, vb + off);
                    LDSM4(c0, c1, c2, c3, vb + 8192u + off);
                    MMAS(oacc[2*p],   pah, b0, b1);
                    MMAS(oacc[2*p+1], pah, b2, b3);
                    MMAS(oacc[2*p],   pah, c0, c1);
                    MMAS(oacc[2*p+1], pah, c2, c3);
                    MMAS(oacc[2*p],   pal, b0, b1);
                    MMAS(oacc[2*p+1], pal, b2, b3);
                }
            }
        }
        __syncthreads();
    }

    // ---- epilogue ----
    float invA = 1.f / lA, invB = 1.f / lB;
    size_t rowA = (size_t)(b * TT + qrA);
    size_t rowB = rowA + 8;
    int colb = h * HD + (lid & 3) * 2;
    #pragma unroll
    for (int nt = 0; nt < 8; nt++) {
        uint32_t hi, lo;
        split2(oacc[nt][0] * invA, oacc[nt][1] * invA, hi, lo);
        *(uint32_t*)&Ohi[rowA * DD + colb + nt * 8] = hi;
        *(uint32_t*)&Olo[rowA * DD + colb + nt * 8] = lo;
        split2(oacc[nt][2] * invB, oacc[nt][3] * invB, hi, lo);
        *(uint32_t*)&Ohi[rowB * DD + colb + nt * 8] = hi;
        *(uint32_t*)&Olo[rowB * DD + colb + nt * 8] = lo;
    }
}

// ---------------------------------------------------------------------------
// prep: fused x split + 4 weight transposes + rope table (sections on blockIdx.x)
// ---------------------------------------------------------------------------
__device__ __forceinline__ void convT_body(const float* __restrict__ W,
        __nv_bfloat16* __restrict__ thi, __nv_bfloat16* __restrict__ tlo,
        int Kd, int Nd, int idx, int tid, float (*Ts)[33]) {
    int nt = idx % (Nd / 32), kt = idx / (Nd / 32);
    int k0 = kt * 32, n0 = nt * 32;
    int r = tid >> 3, c4 = (tid & 7) * 4;
    float4 v = *(const float4*)&W[(size_t)(k0 + r) * Nd + n0 + c4];
    Ts[r][c4] = v.x; Ts[r][c4 + 1] = v.y; Ts[r][c4 + 2] = v.z; Ts[r][c4 + 3] = v.w;
    __syncthreads();
    #pragma unroll
    for (int j = 0; j < 4; j++) {
        float x = Ts[c4 + j][r];
        __nv_bfloat16 h = __float2bfloat16(x);
        size_t o = (size_t)(n0 + r) * Kd + k0 + c4 + j;
        thi[o] = h;
        tlo[o] = __float2bfloat16(x - __bfloat162float(h));
    }
}

__global__ __launch_bounds__(256) void prep(const float* __restrict__ x,
        const float* __restrict__ Wq, const float* __restrict__ Wk,
        const float* __restrict__ Wv, const float* __restrict__ Wo) {
    __shared__ float Ts[32][33];
    int bx = blockIdx.x, tid = threadIdx.x;
    if (bx < 4096) {                       // x hi/lo split
        int i = (bx * 256 + tid) * 4;
        float4 v = *(const float4*)(x + i);
        float vv[4] = {v.x, v.y, v.z, v.w};
        #pragma unroll
        for (int j = 0; j < 4; j++) {
            __nv_bfloat16 h = __float2bfloat16(vv[j]);
            g_xhi[i + j] = h;
            g_xlo[i + j] = __float2bfloat16(vv[j] - __bfloat162float(h));
        }
    } else if (bx < 5120) {
        convT_body(Wq, g_wt_hi, g_wt_lo, DD, DD, bx - 4096, tid, Ts);
    } else if (bx < 5376) {
        convT_body(Wk, g_wt_hi + (size_t)NH * HD * DD, g_wt_lo + (size_t)NH * HD * DD,
                   DD, NKV * HD, bx - 5120, tid, Ts);
    } else if (bx < 5632) {
        convT_body(Wv, g_wt_hi + (size_t)(NH + NKV) * HD * DD,
                   g_wt_lo + (size_t)(NH + NKV) * HD * DD, DD, NKV * HD, bx - 5376, tid, Ts);
    } else if (bx < 6656) {
        convT_body(Wo, g_wot_hi, g_wot_lo, DD, DD, bx - 5632, tid, Ts);
    } else {                               // rope table
        int idx = (bx - 6656) * 256 + tid;
        int t = idx >> 5, pair = idx & 31;
        float freq = (float)pow(500000.0, -(double)pair / 32.0);
        float ang = (float)t * freq;
        g_cos[idx] = (float)cos((double)ang);
        g_sin[idx] = (float)sin((double)ang);
    }
}

// ---------------------------------------------------------------------------
// rope_vt: fused Q+K RoPE-split + V transpose-split
// ---------------------------------------------------------------------------
__global__ __launch_bounds__(256) void rope_vt() {
    __shared__ float Ts[32][33];
    int bx = blockIdx.x, tid = threadIdx.x;
    if (bx < 5120) {                       // Q+K rope: heads 0..19 (K at cols 1024+)
        int u = bx * 256 + tid;
        int d4 = (u & 15) * 4;
        int t = (u >> 4) % TT;
        int hh = ((u >> 4) / TT) % (NH + NKV);
        int b = u / (16 * TT * (NH + NKV));
        float4 v = *(const float4*)&g_qkv[(size_t)(b * TT + t) * NQKV + hh * HD + d4];
        int ci = t * 32 + d4 / 2;
        float2 cs = *(const float2*)&g_cos[ci];
        float2 sn = *(const float2*)&g_sin[ci];
        float r[4];
        r[0] = v.x * cs.x - v.y * sn.x;
        r[1] = v.y * cs.x + v.x * sn.x;
        r[2] = v.z * cs.y - v.w * sn.y;
        r[3] = v.w * cs.y + v.z * sn.y;
        __nv_bfloat16 *hi, *lo;
        size_t o;
        if (hh < NH) {
            o = ((size_t)(b * NH + hh) * TT + t) * HD + d4;
            hi = g_qhi; lo = g_qlo;
        } else {
            o = ((size_t)(b * NKV + hh - NH) * TT + t) * HD + d4;
            hi = g_khi; lo = g_klo;
        }
        #pragma unroll
        for (int j = 0; j < 4; j++) {
            __nv_bfloat16 hv = __float2bfloat16(r[j]);
            hi[o + j] = hv;
            lo[o + j] = __float2bfloat16(r[j] - __bfloat162float(hv));
        }
    } else {                               // V transpose-split
        int idx = bx - 5120;               // 64 t-tiles x 2 d-tiles x BB*NKV
        int t0 = (idx % 64) * 32;
        int d0 = ((idx / 64) & 1) * 32;
        int bk = idx / 128;
        int b = bk / NKV, kv = bk % NKV;
        int r = tid >> 3, c4 = (tid & 7) * 4;
        float4 v = *(const float4*)&g_qkv[(size_t)(b * TT + t0 + r) * NQKV
                                          + NH * HD + NKV * HD + kv * HD + d0 + c4];
        Ts[r][c4] = v.x; Ts[r][c4 + 1] = v.y; Ts[r][c4 + 2] = v.z; Ts[r][c4 + 3] = v.w;
        __syncthreads();
        int dr = tid >> 3, t4 = (tid & 7) * 4;
        size_t o = ((size_t)(b * NKV + kv) * HD + d0 + dr) * TT + t0 + t4;
        #pragma unroll
        for (int j = 0; j < 4; j++) {
            float xv = Ts[t4 + j][dr];
            __nv_bfloat16 h = __float2bfloat16(xv);
            g_vthi[o + j] = h;
            g_vtlo[o + j] = __float2bfloat16(xv - __bfloat162float(h));
        }
    }
}

// ---------------------------------------------------------------------------
extern "C" void kernel_launch(void* const* d_in, const int* in_sizes, int n_in,
                              void* d_out, int out_size) {
    const float* x  = (const float*)d_in[0];
    // d_in[1] = causal mask — handled analytically
    const float* Wq = (const float*)d_in[2];
    const float* Wk = (const float*)d_in[3];
    const float* Wv = (const float*)d_in[4];
    const float* Wo = (const float*)d_in[5];
    float* out = (float*)d_out;

    float *qkv;
    __nv_bfloat16 *xhi, *xlo, *ahi, *alo, *wth, *wtl, *woh, *wol;
    __nv_bfloat16 *qhi, *qlo, *khi, *klo, *vthi, *vtlo;
    cudaGetSymbolAddress((void**)&qkv, g_qkv);
    cudaGetSymbolAddress((void**)&xhi, g_xhi);
    cudaGetSymbolAddress((void**)&xlo, g_xlo);
    cudaGetSymbolAddress((void**)&ahi, g_ahi);
    cudaGetSymbolAddress((void**)&alo, g_alo);
    cudaGetSymbolAddress((void**)&wth, g_wt_hi);
    cudaGetSymbolAddress((void**)&wtl, g_wt_lo);
    cudaGetSymbolAddress((void**)&woh, g_wot_hi);
    cudaGetSymbolAddress((void**)&wol, g_wot_lo);
    cudaGetSymbolAddress((void**)&qhi, g_qhi);
    cudaGetSymbolAddress((void**)&qlo, g_qlo);
    cudaGetSymbolAddress((void**)&khi, g_khi);
    cudaGetSymbolAddress((void**)&klo, g_klo);
    cudaGetSymbolAddress((void**)&vthi, g_vthi);
    cudaGetSymbolAddress((void**)&vtlo, g_vtlo);

    cudaFuncSetAttribute(gemm_mma, cudaFuncAttributeMaxDynamicSharedMemorySize, 196608);
    cudaFuncSetAttribute(attn_mma, cudaFuncAttributeMaxDynamicSharedMemorySize, 131072);

    prep<<<6912, 256>>>(x, Wq, Wk, Wv, Wo);

    // fused QKV projection: [4096,1024] @ [1024,1536]
    gemm_mma<<<dim3(NQKV / 256, MM / 128), 256, 196608>>>(xhi, xlo, wth, wtl,
                                                          qkv, MM, NQKV, DD);

    rope_vt<<<5120 + 1024, 256>>>();

    attn_mma<<<dim3(TT / 128, BB * NH), 256, 131072>>>(qhi, qlo, khi, klo,
                                                       vthi, vtlo, ahi, alo);

    gemm_mma<<<dim3(DD / 256, MM / 128), 256, 196608>>>(ahi, alo, woh, wol,
                                                        out, MM, DD, DD);
}

// round 7
// speedup vs baseline: 1.1956x; 1.1956x over previous
#include <cuda_runtime.h>
#include <cuda_bf16.h>
#include <cuda_fp16.h>
#include <math.h>
#include <stdint.h>

#define BB 2
#define TT 2048
#define DD 1024
#define NH 16
#define NKV 4
#define HD 64
#define NREP 4           // NH / NKV
#define MM (BB*TT)       // 4096
#define NQKV (NH*HD + 2*NKV*HD)   // 1536 fused QKV output width

// ---------------- scratch (device globals; no runtime allocation) -----------
__device__ float g_qkv[MM*NQKV];            // fused QKV proj out (fp32)
__device__ __align__(16) float g_cos[TT*32];
__device__ __align__(16) float g_sin[TT*32];
__device__ __nv_bfloat16 g_xhi[MM*DD],  g_xlo[MM*DD];
__device__ __nv_bfloat16 g_ahi[MM*DD],  g_alo[MM*DD];          // attention out (bf16 split)
__device__ __nv_bfloat16 g_wt_hi[NQKV*DD], g_wt_lo[NQKV*DD];   // fused QKV weights^T [N][K]
__device__ __nv_bfloat16 g_wot_hi[DD*DD],  g_wot_lo[DD*DD];    // Wo^T [N][K]
__device__ __nv_bfloat16 g_qhi[BB*NH*TT*HD],  g_qlo[BB*NH*TT*HD];
__device__ __nv_bfloat16 g_khi[BB*NKV*TT*HD], g_klo[BB*NKV*TT*HD];
__device__ __half g_vt[BB*NKV*HD*TT];       // V^T fp16 [b][kvh][d][t]

// ---------------- helpers ----------------------------------------------------
__device__ __forceinline__ uint32_t smem_u32(const void* p) {
    uint32_t a;
    asm("{ .reg .u64 t; cvta.to.shared.u64 t, %1; cvt.u32.u64 %0, t; }"
        : "=r"(a) : "l"(p));
    return a;
}
#define SWZ(off) ((off) ^ (((off) >> 3) & 0x70))

#define CP_ASYNC16(dst, src) \
    asm volatile("cp.async.cg.shared.global [%0], [%1], 16;" \
                 :: "r"(dst), "l"(src) : "memory")
#define CP_COMMIT() asm volatile("cp.async.commit_group;" ::: "memory")
#define CP_WAIT(n)  asm volatile("cp.async.wait_group %0;" :: "n"(n) : "memory")

#define LDSM4(r0, r1, r2, r3, addr) \
    asm volatile("ldmatrix.sync.aligned.m8n8.x4.shared.b16 {%0,%1,%2,%3}, [%4];" \
                 : "=r"(r0), "=r"(r1), "=r"(r2), "=r"(r3) : "r"(addr))

#define MMAS(c, a, b0, b1) \
    asm volatile("mma.sync.aligned.m16n8k16.row.col.f32.bf16.bf16.f32 " \
                 "{%0,%1,%2,%3}, {%4,%5,%6,%7}, {%8,%9}, {%0,%1,%2,%3};" \
                 : "+f"((c)[0]), "+f"((c)[1]), "+f"((c)[2]), "+f"((c)[3]) \
                 : "r"((a)[0]), "r"((a)[1]), "r"((a)[2]), "r"((a)[3]), \
                   "r"(b0), "r"(b1))

#define MMAH(c, a, b0, b1) \
    asm volatile("mma.sync.aligned.m16n8k16.row.col.f32.f16.f16.f32 " \
                 "{%0,%1,%2,%3}, {%4,%5,%6,%7}, {%8,%9}, {%0,%1,%2,%3};" \
                 : "+f"((c)[0]), "+f"((c)[1]), "+f"((c)[2]), "+f"((c)[3]) \
                 : "r"((a)[0]), "r"((a)[1]), "r"((a)[2]), "r"((a)[3]), \
                   "r"(b0), "r"(b1))

__device__ __forceinline__ void split2(float x0, float x1, uint32_t& hi, uint32_t& lo) {
    __nv_bfloat16 h0 = __float2bfloat16(x0), h1 = __float2bfloat16(x1);
    float r0 = x0 - __bfloat162float(h0), r1 = x1 - __bfloat162float(h1);
    __nv_bfloat162 H; H.x = h0; H.y = h1;
    __nv_bfloat162 L = __floats2bfloat162_rn(r0, r1);
    hi = *(uint32_t*)&H; lo = *(uint32_t*)&L;
}

__device__ __forceinline__ uint32_t packh(float a, float b) {
    __half2 h = __floats2half2_rn(a, b);
    return *(uint32_t*)&h;
}

// ---------------------------------------------------------------------------
// Split-bf16 HMMA GEMM: C[M,N] = (Ahi+Alo)[M,K] @ (Bhi+Blo)[N,K]^T (fp32 acc)
// 128x128 CTA tile, 8 warps (2m x 4n, warp tile 64x32), BK=64,
// cp.async 3-stage (3 x 64KB smem), prefetch before compute.
// ---------------------------------------------------------------------------
__global__ __launch_bounds__(256, 1) void gemm_mma(
        const __nv_bfloat16* __restrict__ Ahi, const __nv_bfloat16* __restrict__ Alo,
        const __nv_bfloat16* __restrict__ Bhi, const __nv_bfloat16* __restrict__ Blo,
        float* __restrict__ C, int M, int N, int K) {
    extern __shared__ char smem[];
    uint32_t sbase = smem_u32(smem);
    int tid = threadIdx.x, wid = tid >> 5, lid = tid & 31;
    int m0 = blockIdx.y * 128, n0 = blockIdx.x * 128;
    int wm = wid & 1, wn = wid >> 1;
    const int nch = K / 64;
    const int rr = tid >> 3;
    const int uu = tid & 7;

    float acc[4][4][4] = {};

    auto load_chunk = [&](int buf, int ch) {
        int k0 = ch * 64;
        uint32_t dbase = sbase + (uint32_t)buf * 65536u;
        #pragma unroll
        for (int arr = 0; arr < 4; arr++) {
            const __nv_bfloat16* s = (arr == 0) ? Ahi : (arr == 1) ? Alo
                                    : (arr == 2) ? Bhi : Blo;
            int rb = (arr < 2) ? m0 : n0;
            uint32_t ab = dbase + (uint32_t)arr * 16384u;
            #pragma unroll
            for (int it = 0; it < 4; it++) {
                int r = it * 32 + rr;
                CP_ASYNC16(ab + SWZ(r * 128 + uu * 16),
                           s + (size_t)(rb + r) * K + k0 + uu * 8);
            }
        }
        CP_COMMIT();
    };

    load_chunk(0, 0);
    load_chunk(1, 1);

    for (int ch = 0; ch < nch; ch++) {
        if (ch < nch - 1) { CP_WAIT(1); } else { CP_WAIT(0); }
        __syncthreads();
        if (ch + 2 < nch) load_chunk((ch + 2) % 3, ch + 2);   // early prefetch

        uint32_t db = sbase + (uint32_t)(ch % 3) * 65536u;
        uint32_t abh = db, abl = db + 16384u;
        uint32_t bbh = db + 32768u, bbl = db + 49152u;
        int g = lid >> 3, w8 = lid & 7;

        #pragma unroll
        for (int ks = 0; ks < 4; ks++) {
            uint32_t ah[4][4], al[4][4], bh[4][2], bl[4][2];
            int arow = wm * 64 + (lid & 15);
            int acol = ks * 32 + (lid >> 4) * 16;
            #pragma unroll
            for (int mi = 0; mi < 4; mi++) {
                uint32_t off = SWZ((arow + mi * 16) * 128 + acol);
                LDSM4(ah[mi][0], ah[mi][1], ah[mi][2], ah[mi][3], abh + off);
                LDSM4(al[mi][0], al[mi][1], al[mi][2], al[mi][3], abl + off);
            }
            #pragma unroll
            for (int p = 0; p < 2; p++) {
                int nrow = wn * 32 + p * 16 + (g >> 1) * 8 + w8;
                int ncol = ks * 32 + (g & 1) * 16;
                uint32_t off = SWZ(nrow * 128 + ncol);
                LDSM4(bh[2*p][0], bh[2*p][1], bh[2*p+1][0], bh[2*p+1][1], bbh + off);
                LDSM4(bl[2*p][0], bl[2*p][1], bl[2*p+1][0], bl[2*p+1][1], bbl + off);
            }
            #pragma unroll
            for (int mi = 0; mi < 4; mi++)
                #pragma unroll
                for (int ni = 0; ni < 4; ni++) {
                    MMAS(acc[mi][ni], ah[mi], bh[ni][0], bh[ni][1]);
                    MMAS(acc[mi][ni], ah[mi], bl[ni][0], bl[ni][1]);
                    MMAS(acc[mi][ni], al[mi], bh[ni][0], bh[ni][1]);
                }
        }
        __syncthreads();
    }

    #pragma unroll
    for (int mi = 0; mi < 4; mi++) {
        int row = m0 + wm * 64 + mi * 16 + (lid >> 2);
        #pragma unroll
        for (int ni = 0; ni < 4; ni++) {
            int col = n0 + wn * 32 + ni * 8 + (lid & 3) * 2;
            *(float2*)&C[(size_t)row * N + col] =
                make_float2(acc[mi][ni][0], acc[mi][ni][1]);
            *(float2*)&C[(size_t)(row + 8) * N + col] =
                make_float2(acc[mi][ni][2], acc[mi][ni][3]);
        }
    }
}

// ---------------------------------------------------------------------------
// HMMA flash attention, causal. Grid (T/128 reversed, B*NH), 256 threads.
// S = QK^T 3-term split bf16; PV single-term fp16 (P fp16, V fp16).
// 3-stage cp.async pipeline; exp2-domain softmax; fp32 accum.
// smem: Q 32KB + 3 x 24KB buffers (Khi 8K | Klo 8K | V 8K) = 104KB.
// ---------------------------------------------------------------------------
__global__ __launch_bounds__(256, 1) void attn_mma(
        const __nv_bfloat16* __restrict__ Qhi, const __nv_bfloat16* __restrict__ Qlo,
        const __nv_bfloat16* __restrict__ Khi, const __nv_bfloat16* __restrict__ Klo,
        const __half* __restrict__ Vt,
        __nv_bfloat16* __restrict__ Ohi, __nv_bfloat16* __restrict__ Olo) {
    extern __shared__ char smem[];
    uint32_t sbase = smem_u32(smem);
    const uint32_t QHI = 0, QLO = 16384, BUF = 32768;   // 3 x 24KB chunk buffers

    int tid = threadIdx.x, wid = tid >> 5, lid = tid & 31;
    int qt = gridDim.x - 1 - blockIdx.x;
    int bh = blockIdx.y;
    int b = bh / NH, h = bh % NH, kvh = h / NREP;
    int q0 = qt * 128;

    const __nv_bfloat16* qbh = Qhi + (size_t)(b * NH + h) * TT * HD;
    const __nv_bfloat16* qbl = Qlo + (size_t)(b * NH + h) * TT * HD;
    const __nv_bfloat16* kbh = Khi + (size_t)(b * NKV + kvh) * TT * HD;
    const __nv_bfloat16* kbl = Klo + (size_t)(b * NKV + kvh) * TT * HD;
    const __half* vbase = Vt + (size_t)(b * NKV + kvh) * HD * TT;

    // stage Q (own commit group)
    {
        #pragma unroll
        for (int arr = 0; arr < 2; arr++) {
            const __nv_bfloat16* s = arr ? qbl : qbh;
            uint32_t ab = sbase + (arr ? QLO : QHI);
            #pragma unroll
            for (int it = 0; it < 4; it++) {
                int idx = it * 256 + tid;
                int r = idx >> 3, u = idx & 7;
                CP_ASYNC16(ab + SWZ(r * 128 + u * 16),
                           s + (size_t)(q0 + r) * HD + u * 8);
            }
        }
        CP_COMMIT();
    }

    auto load_chunk = [&](int buf, int kt) {
        uint32_t db = sbase + BUF + (uint32_t)buf * 24576u;
        #pragma unroll
        for (int arr = 0; arr < 3; arr++) {
            uint32_t ab = db + (uint32_t)arr * 8192u;
            #pragma unroll
            for (int it = 0; it < 2; it++) {
                int idx = it * 256 + tid;
                int r = idx >> 3, u = idx & 7;
                const char* src;
                if (arr == 0)      src = (const char*)(kbh + (size_t)(kt * 64 + r) * HD + u * 8);
                else if (arr == 1) src = (const char*)(kbl + (size_t)(kt * 64 + r) * HD + u * 8);
                else               src = (const char*)(vbase + (size_t)r * TT + kt * 64 + u * 8);
                CP_ASYNC16(ab + SWZ(r * 128 + u * 16), src);
            }
        }
        CP_COMMIT();
    };

    int nch = 2 * qt + 2;
    load_chunk(0, 0);
    load_chunk(1, 1);

    // Q fragments (leave both chunk groups pending)
    CP_WAIT(2);
    __syncthreads();
    uint32_t qfh[4][4], qfl[4][4];
    {
        int arow = wid * 16 + (lid & 15);
        #pragma unroll
        for (int ks = 0; ks < 4; ks++) {
            uint32_t off = SWZ(arow * 128 + ks * 32 + (lid >> 4) * 16);
            LDSM4(qfh[ks][0], qfh[ks][1], qfh[ks][2], qfh[ks][3], sbase + QHI + off);
            LDSM4(qfl[ks][0], qfl[ks][1], qfl[ks][2], qfl[ks][3], sbase + QLO + off);
        }
    }

    float oacc[8][4] = {};
    float mA = -1e30f, mB = -1e30f, lA = 0.f, lB = 0.f;
    const int g = lid >> 3, w8 = lid & 7;
    const int qrA = q0 + wid * 16 + (lid >> 2);
    const float SC = 0.125f * 1.4426950408889634f;   // scale * log2(e)

    for (int ch = 0; ch < nch; ch++) {
        if (ch < nch - 1) { CP_WAIT(1); } else { CP_WAIT(0); }
        __syncthreads();
        if (ch + 2 < nch) load_chunk((ch + 2) % 3, ch + 2);   // early prefetch

        int kt = ch;
        bool active = (kt * 64 <= q0 + wid * 16 + 15);
        if (active) {
            uint32_t kb = sbase + BUF + (uint32_t)(ch % 3) * 24576u;
            uint32_t vb = kb + 16384u;

            // ---- S = Q K^T (3-term split bf16) ----
            float sacc[8][4] = {};
            #pragma unroll
            for (int ks = 0; ks < 4; ks++) {
                #pragma unroll
                for (int p = 0; p < 4; p++) {
                    int nrow = p * 16 + (g >> 1) * 8 + w8;
                    uint32_t off = SWZ(nrow * 128 + ks * 32 + (g & 1) * 16);
                    uint32_t b0, b1, b2, b3, c0, c1, c2, c3;
                    LDSM4(b0, b1, b2, b3, kb + off);
                    LDSM4(c0, c1, c2, c3, kb + 8192u + off);
                    MMAS(sacc[2*p],   qfh[ks], b0, b1);
                    MMAS(sacc[2*p+1], qfh[ks], b2, b3);
                    MMAS(sacc[2*p],   qfh[ks], c0, c1);
                    MMAS(sacc[2*p+1], qfh[ks], c2, c3);
                    MMAS(sacc[2*p],   qfl[ks], b0, b1);
                    MMAS(sacc[2*p+1], qfl[ks], b2, b3);
                }
            }

            // ---- scale (log2 domain) + causal mask ----
            #pragma unroll
            for (int nt = 0; nt < 8; nt++) {
                int kc = kt * 64 + nt * 8 + (lid & 3) * 2;
                #pragma unroll
                for (int j = 0; j < 4; j++) sacc[nt][j] *= SC;
                if (kc > qrA)         sacc[nt][0] = -1e9f;
                if (kc + 1 > qrA)     sacc[nt][1] = -1e9f;
                if (kc > qrA + 8)     sacc[nt][2] = -1e9f;
                if (kc + 1 > qrA + 8) sacc[nt][3] = -1e9f;
            }

            // ---- online softmax (base-2) ----
            float rmA = -1e30f, rmB = -1e30f;
            #pragma unroll
            for (int nt = 0; nt < 8; nt++) {
                rmA = fmaxf(rmA, fmaxf(sacc[nt][0], sacc[nt][1]));
                rmB = fmaxf(rmB, fmaxf(sacc[nt][2], sacc[nt][3]));
            }
            rmA = fmaxf(rmA, __shfl_xor_sync(0xffffffffu, rmA, 1));
            rmA = fmaxf(rmA, __shfl_xor_sync(0xffffffffu, rmA, 2));
            rmB = fmaxf(rmB, __shfl_xor_sync(0xffffffffu, rmB, 1));
            rmB = fmaxf(rmB, __shfl_xor_sync(0xffffffffu, rmB, 2));
            float mnA = fmaxf(mA, rmA), mnB = fmaxf(mB, rmB);
            float corrA = exp2f(mA - mnA), corrB = exp2f(mB - mnB);
            mA = mnA; mB = mnB;
            float rsA = 0.f, rsB = 0.f;
            #pragma unroll
            for (int nt = 0; nt < 8; nt++) {
                sacc[nt][0] = exp2f(sacc[nt][0] - mA);
                sacc[nt][1] = exp2f(sacc[nt][1] - mA);
                sacc[nt][2] = exp2f(sacc[nt][2] - mB);
                sacc[nt][3] = exp2f(sacc[nt][3] - mB);
                rsA += sacc[nt][0] + sacc[nt][1];
                rsB += sacc[nt][2] + sacc[nt][3];
            }
            rsA += __shfl_xor_sync(0xffffffffu, rsA, 1);
            rsA += __shfl_xor_sync(0xffffffffu, rsA, 2);
            rsB += __shfl_xor_sync(0xffffffffu, rsB, 1);
            rsB += __shfl_xor_sync(0xffffffffu, rsB, 2);
            lA = lA * corrA + rsA;
            lB = lB * corrB + rsB;
            #pragma unroll
            for (int nt = 0; nt < 8; nt++) {
                oacc[nt][0] *= corrA; oacc[nt][1] *= corrA;
                oacc[nt][2] *= corrB; oacc[nt][3] *= corrB;
            }

            // ---- O += P V (single-term fp16) ----
            #pragma unroll
            for (int k2 = 0; k2 < 4; k2++) {
                uint32_t pa[4];
                pa[0] = packh(sacc[2*k2][0],   sacc[2*k2][1]);
                pa[1] = packh(sacc[2*k2][2],   sacc[2*k2][3]);
                pa[2] = packh(sacc[2*k2+1][0], sacc[2*k2+1][1]);
                pa[3] = packh(sacc[2*k2+1][2], sacc[2*k2+1][3]);
                #pragma unroll
                for (int p = 0; p < 4; p++) {
                    int nrow = p * 16 + (g >> 1) * 8 + w8;
                    uint32_t off = SWZ(nrow * 128 + k2 * 32 + (g & 1) * 16);
                    uint32_t b0, b1, b2, b3;
                    LDSM4(b0, b1, b2, b3, vb + off);
                    MMAH(oacc[2*p],   pa, b0, b1);
                    MMAH(oacc[2*p+1], pa, b2, b3);
                }
            }
        }
        __syncthreads();
    }

    // ---- epilogue ----
    float invA = 1.f / lA, invB = 1.f / lB;
    size_t rowA = (size_t)(b * TT + qrA);
    size_t rowB = rowA + 8;
    int colb = h * HD + (lid & 3) * 2;
    #pragma unroll
    for (int nt = 0; nt < 8; nt++) {
        uint32_t hi, lo;
        split2(oacc[nt][0] * invA, oacc[nt][1] * invA, hi, lo);
        *(uint32_t*)&Ohi[rowA * DD + colb + nt * 8] = hi;
        *(uint32_t*)&Olo[rowA * DD + colb + nt * 8] = lo;
        split2(oacc[nt][2] * invB, oacc[nt][3] * invB, hi, lo);
        *(uint32_t*)&Ohi[rowB * DD + colb + nt * 8] = hi;
        *(uint32_t*)&Olo[rowB * DD + colb + nt * 8] = lo;
    }
}

// ---------------------------------------------------------------------------
// prep: fused x split + 4 weight transposes + rope table (sections on blockIdx.x)
// ---------------------------------------------------------------------------
__device__ __forceinline__ void convT_body(const float* __restrict__ W,
        __nv_bfloat16* __restrict__ thi, __nv_bfloat16* __restrict__ tlo,
        int Kd, int Nd, int idx, int tid, float (*Ts)[33]) {
    int nt = idx % (Nd / 32), kt = idx / (Nd / 32);
    int k0 = kt * 32, n0 = nt * 32;
    int r = tid >> 3, c4 = (tid & 7) * 4;
    float4 v = *(const float4*)&W[(size_t)(k0 + r) * Nd + n0 + c4];
    Ts[r][c4] = v.x; Ts[r][c4 + 1] = v.y; Ts[r][c4 + 2] = v.z; Ts[r][c4 + 3] = v.w;
    __syncthreads();
    #pragma unroll
    for (int j = 0; j < 4; j++) {
        float x = Ts[c4 + j][r];
        __nv_bfloat16 h = __float2bfloat16(x);
        size_t o = (size_t)(n0 + r) * Kd + k0 + c4 + j;
        thi[o] = h;
        tlo[o] = __float2bfloat16(x - __bfloat162float(h));
    }
}

__global__ __launch_bounds__(256) void prep(const float* __restrict__ x,
        const float* __restrict__ Wq, const float* __restrict__ Wk,
        const float* __restrict__ Wv, const float* __restrict__ Wo) {
    __shared__ float Ts[32][33];
    int bx = blockIdx.x, tid = threadIdx.x;
    if (bx < 4096) {                       // x hi/lo split
        int i = (bx * 256 + tid) * 4;
        float4 v = *(const float4*)(x + i);
        float vv[4] = {v.x, v.y, v.z, v.w};
        #pragma unroll
        for (int j = 0; j < 4; j++) {
            __nv_bfloat16 h = __float2bfloat16(vv[j]);
            g_xhi[i + j] = h;
            g_xlo[i + j] = __float2bfloat16(vv[j] - __bfloat162float(h));
        }
    } else if (bx < 5120) {
        convT_body(Wq, g_wt_hi, g_wt_lo, DD, DD, bx - 4096, tid, Ts);
    } else if (bx < 5376) {
        convT_body(Wk, g_wt_hi + (size_t)NH * HD * DD, g_wt_lo + (size_t)NH * HD * DD,
                   DD, NKV * HD, bx - 5120, tid, Ts);
    } else if (bx < 5632) {
        convT_body(Wv, g_wt_hi + (size_t)(NH + NKV) * HD * DD,
                   g_wt_lo + (size_t)(NH + NKV) * HD * DD, DD, NKV * HD, bx - 5376, tid, Ts);
    } else if (bx < 6656) {
        convT_body(Wo, g_wot_hi, g_wot_lo, DD, DD, bx - 5632, tid, Ts);
    } else {                               // rope table
        int idx = (bx - 6656) * 256 + tid;
        int t = idx >> 5, pair = idx & 31;
        float freq = (float)pow(500000.0, -(double)pair / 32.0);
        float ang = (float)t * freq;
        g_cos[idx] = (float)cos((double)ang);
        g_sin[idx] = (float)sin((double)ang);
    }
}

// ---------------------------------------------------------------------------
// rope_vt: fused Q+K RoPE-split + V transpose (fp16)
// ---------------------------------------------------------------------------
__global__ __launch_bounds__(256) void rope_vt() {
    __shared__ float Ts[32][33];
    int bx = blockIdx.x, tid = threadIdx.x;
    if (bx < 5120) {                       // Q+K rope: heads 0..19 (K at cols 1024+)
        int u = bx * 256 + tid;
        int d4 = (u & 15) * 4;
        int t = (u >> 4) % TT;
        int hh = ((u >> 4) / TT) % (NH + NKV);
        int b = u / (16 * TT * (NH + NKV));
        float4 v = *(const float4*)&g_qkv[(size_t)(b * TT + t) * NQKV + hh * HD + d4];
        int ci = t * 32 + d4 / 2;
        float2 cs = *(const float2*)&g_cos[ci];
        float2 sn = *(const float2*)&g_sin[ci];
        float r[4];
        r[0] = v.x * cs.x - v.y * sn.x;
        r[1] = v.y * cs.x + v.x * sn.x;
        r[2] = v.z * cs.y - v.w * sn.y;
        r[3] = v.w * cs.y + v.z * sn.y;
        __nv_bfloat16 *hi, *lo;
        size_t o;
        if (hh < NH) {
            o = ((size_t)(b * NH + hh) * TT + t) * HD + d4;
            hi = g_qhi; lo = g_qlo;
        } else {
            o = ((size_t)(b * NKV + hh - NH) * TT + t) * HD + d4;
            hi = g_khi; lo = g_klo;
        }
        #pragma unroll
        for (int j = 0; j < 4; j++) {
            __nv_bfloat16 hv = __float2bfloat16(r[j]);
            hi[o + j] = hv;
            lo[o + j] = __float2bfloat16(r[j] - __bfloat162float(hv));
        }
    } else {                               // V transpose (fp16)
        int idx = bx - 5120;               // 64 t-tiles x 2 d-tiles x BB*NKV
        int t0 = (idx % 64) * 32;
        int d0 = ((idx / 64) & 1) * 32;
        int bk = idx / 128;
        int b = bk / NKV, kv = bk % NKV;
        int r = tid >> 3, c4 = (tid & 7) * 4;
        float4 v = *(const float4*)&g_qkv[(size_t)(b * TT + t0 + r) * NQKV
                                          + NH * HD + NKV * HD + kv * HD + d0 + c4];
        Ts[r][c4] = v.x; Ts[r][c4 + 1] = v.y; Ts[r][c4 + 2] = v.z; Ts[r][c4 + 3] = v.w;
        __syncthreads();
        int dr = tid >> 3, t4 = (tid & 7) * 4;
        size_t o = ((size_t)(b * NKV + kv) * HD + d0 + dr) * TT + t0 + t4;
        #pragma unroll
        for (int j = 0; j < 4; j++)
            g_vt[o + j] = __float2half(Ts[t4 + j][dr]);
    }
}

// ---------------------------------------------------------------------------
extern "C" void kernel_launch(void* const* d_in, const int* in_sizes, int n_in,
                              void* d_out, int out_size) {
    const float* x  = (const float*)d_in[0];
    // d_in[1] = causal mask — handled analytically
    const float* Wq = (const float*)d_in[2];
    const float* Wk = (const float*)d_in[3];
    const float* Wv = (const float*)d_in[4];
    const float* Wo = (const float*)d_in[5];
    float* out = (float*)d_out;

    float *qkv;
    __nv_bfloat16 *xhi, *xlo, *ahi, *alo, *wth, *wtl, *woh, *wol;
    __nv_bfloat16 *qhi, *qlo, *khi, *klo;
    __half *vt;
    cudaGetSymbolAddress((void**)&qkv, g_qkv);
    cudaGetSymbolAddress((void**)&xhi, g_xhi);
    cudaGetSymbolAddress((void**)&xlo, g_xlo);
    cudaGetSymbolAddress((void**)&ahi, g_ahi);
    cudaGetSymbolAddress((void**)&alo, g_alo);
    cudaGetSymbolAddress((void**)&wth, g_wt_hi);
    cudaGetSymbolAddress((void**)&wtl, g_wt_lo);
    cudaGetSymbolAddress((void**)&woh, g_wot_hi);
    cudaGetSymbolAddress((void**)&wol, g_wot_lo);
    cudaGetSymbolAddress((void**)&qhi, g_qhi);
    cudaGetSymbolAddress((void**)&qlo, g_qlo);
    cudaGetSymbolAddress((void**)&khi, g_khi);
    cudaGetSymbolAddress((void**)&klo, g_klo);
    cudaGetSymbolAddress((void**)&vt,  g_vt);

    cudaFuncSetAttribute(gemm_mma, cudaFuncAttributeMaxDynamicSharedMemorySize, 196608);
    cudaFuncSetAttribute(attn_mma, cudaFuncAttributeMaxDynamicSharedMemorySize, 106496);

    prep<<<6912, 256>>>(x, Wq, Wk, Wv, Wo);

    // fused QKV projection: [4096,1024] @ [1024,1536]
    gemm_mma<<<dim3(NQKV / 128, MM / 128), 256, 196608>>>(xhi, xlo, wth, wtl,
                                                          qkv, MM, NQKV, DD);

    rope_vt<<<5120 + 1024, 256>>>();

    attn_mma<<<dim3(TT / 128, BB * NH), 256, 106496>>>(qhi, qlo, khi, klo,
                                                       vt, ahi, alo);

    gemm_mma<<<dim3(DD / 128, MM / 128), 256, 196608>>>(ahi, alo, woh, wol,
                                                        out, MM, DD, DD);
}